// round 1
// baseline (speedup 1.0000x reference)
#include <cuda_runtime.h>
#include <cuda_bf16.h>
#include <math.h>

// Problem constants (fixed shapes for this problem instance)
#define NTOK 4096   // B*T
#define DDIM 1024   // model dim
#define FDIM 4096   // ffn dim
#define NEXP 8      // experts
#define TOPK 2

#define BM 128
#define BN 128
#define BK 8

// ---------------- device scratch (no runtime allocation allowed) ----------
__device__ int   g_count[NEXP];
__device__ int   g_cursor[NEXP];
__device__ int   g_offset[NEXP];
__device__ int   g_topk_idx[NTOK * TOPK];
__device__ float g_topk_w[NTOK * TOPK];
__device__ int   g_token_of_row[NTOK * TOPK];
__device__ float g_w_of_row[NTOK * TOPK];
__device__ int   g_row_of_token[NTOK * TOPK];
__device__ float g_H[(size_t)NTOK * TOPK * FDIM];   // 134 MB: gelu(x@W1) rows, expert-compact
__device__ float g_Y[(size_t)NTOK * TOPK * DDIM];   // 33.5 MB: w * (H@W2) rows

__device__ __forceinline__ float gelu_exact(float v) {
    return 0.5f * v * (1.0f + erff(v * 0.70710678118654752440f));
}

// ---------------- K0: zero counters ----------------
__global__ void zero_kernel() {
    int t = threadIdx.x;
    if (t < NEXP) { g_count[t] = 0; g_cursor[t] = 0; }
}

// ---------------- K1: router (warp per token) ----------------
__global__ void router_kernel(const float* __restrict__ x,
                              const float* __restrict__ Wr) {
    int gwarp  = (blockIdx.x * blockDim.x + threadIdx.x) >> 5;
    int lane   = threadIdx.x & 31;
    int nwarps = (gridDim.x * blockDim.x) >> 5;

    for (int n = gwarp; n < NTOK; n += nwarps) {
        const float* xr = x + (size_t)n * DDIM;
        float acc[NEXP];
        #pragma unroll
        for (int e = 0; e < NEXP; e++) acc[e] = 0.f;

        for (int d = lane; d < DDIM; d += 32) {
            float xv = xr[d];
            const float* wr = Wr + (size_t)d * NEXP;
            float4 w0 = *(const float4*)(wr);
            float4 w1 = *(const float4*)(wr + 4);
            acc[0] = fmaf(xv, w0.x, acc[0]);
            acc[1] = fmaf(xv, w0.y, acc[1]);
            acc[2] = fmaf(xv, w0.z, acc[2]);
            acc[3] = fmaf(xv, w0.w, acc[3]);
            acc[4] = fmaf(xv, w1.x, acc[4]);
            acc[5] = fmaf(xv, w1.y, acc[5]);
            acc[6] = fmaf(xv, w1.z, acc[6]);
            acc[7] = fmaf(xv, w1.w, acc[7]);
        }
        #pragma unroll
        for (int e = 0; e < NEXP; e++) {
            #pragma unroll
            for (int o = 16; o > 0; o >>= 1)
                acc[e] += __shfl_xor_sync(0xFFFFFFFFu, acc[e], o);
        }
        if (lane == 0) {
            // top-1 (lowest index on tie, like lax.top_k)
            int i0 = 0; float v0 = acc[0];
            #pragma unroll
            for (int e = 1; e < NEXP; e++)
                if (acc[e] > v0) { v0 = acc[e]; i0 = e; }
            int i1 = -1; float v1 = -3.4e38f;
            #pragma unroll
            for (int e = 0; e < NEXP; e++)
                if (e != i0 && acc[e] > v1) { v1 = acc[e]; i1 = e; }
            // softmax over the 2 selected logits (v0 >= v1)
            float e0 = 1.0f;                 // exp(v0 - v0)
            float e1 = __expf(v1 - v0);
            float inv = 1.0f / (e0 + e1);
            g_topk_idx[2 * n + 0] = i0;
            g_topk_idx[2 * n + 1] = i1;
            g_topk_w[2 * n + 0] = e0 * inv;
            g_topk_w[2 * n + 1] = e1 * inv;
            atomicAdd(&g_count[i0], 1);
            atomicAdd(&g_count[i1], 1);
        }
    }
}

// ---------------- K2: tiny prefix sum ----------------
__global__ void prefix_kernel() {
    int s = 0;
    for (int e = 0; e < NEXP; e++) { g_offset[e] = s; s += g_count[e]; }
}

// ---------------- K3: build per-expert row lists ----------------
__global__ void dispatch_kernel() {
    int n = blockIdx.x * blockDim.x + threadIdx.x;
    if (n >= NTOK) return;
    #pragma unroll
    for (int s = 0; s < TOPK; s++) {
        int e   = g_topk_idx[2 * n + s];
        int pos = atomicAdd(&g_cursor[e], 1);
        int row = g_offset[e] + pos;
        g_token_of_row[row] = n;
        g_w_of_row[row]     = g_topk_w[2 * n + s];
        g_row_of_token[2 * n + s] = row;
    }
}

// ---------------- K4: H = gelu(X_gathered @ W1[e]) ----------------
// grid = (FDIM/BN, NTOK/BM, NEXP), block = 256
__global__ __launch_bounds__(256) void gemm1_kernel(const float* __restrict__ X,
                                                    const float* __restrict__ W1all) {
    const int e   = blockIdx.z;
    const int cnt = g_count[e];
    const int m0  = blockIdx.y * BM;
    if (m0 >= cnt) return;
    const int n0  = blockIdx.x * BN;
    const int off = g_offset[e];
    const float* Bmat = W1all + (size_t)e * DDIM * FDIM;

    __shared__ float As[2][BK][BM];
    __shared__ float Bs[2][BK][BN];
    __shared__ int   toks[BM];

    const int tid = threadIdx.x;
    if (tid < BM) {
        int r = m0 + tid;
        toks[tid] = (r < cnt) ? g_token_of_row[off + r] : -1;
    }
    __syncthreads();

    const int la_m = tid >> 1;
    const int la_k = (tid & 1) * 4;
    const int lb_k = tid >> 5;
    const int lb_n = (tid & 31) * 4;
    const int tx   = tid & 15;
    const int ty   = tid >> 4;

    const int  tokA   = toks[la_m];
    const bool avalid = (tokA >= 0);
    const float* aptr = X + (size_t)(avalid ? tokA : 0) * DDIM;

    float acc[8][8];
    #pragma unroll
    for (int i = 0; i < 8; i++)
        #pragma unroll
        for (int j = 0; j < 8; j++) acc[i][j] = 0.f;

    float4 av = avalid ? *(const float4*)(aptr + la_k) : make_float4(0, 0, 0, 0);
    float4 bv = *(const float4*)(Bmat + (size_t)lb_k * FDIM + n0 + lb_n);
    As[0][la_k + 0][la_m] = av.x;
    As[0][la_k + 1][la_m] = av.y;
    As[0][la_k + 2][la_m] = av.z;
    As[0][la_k + 3][la_m] = av.w;
    *(float4*)&Bs[0][lb_k][lb_n] = bv;
    __syncthreads();

    int buf = 0;
    #pragma unroll 1
    for (int k0 = 0; k0 < DDIM; k0 += BK) {
        const int kn = k0 + BK;
        if (kn < DDIM) {
            av = avalid ? *(const float4*)(aptr + kn + la_k) : make_float4(0, 0, 0, 0);
            bv = *(const float4*)(Bmat + (size_t)(kn + lb_k) * FDIM + n0 + lb_n);
        }
        #pragma unroll
        for (int k = 0; k < BK; k++) {
            float4 a0 = *(const float4*)&As[buf][k][ty * 8];
            float4 a1 = *(const float4*)&As[buf][k][ty * 8 + 4];
            float4 b0 = *(const float4*)&Bs[buf][k][tx * 8];
            float4 b1 = *(const float4*)&Bs[buf][k][tx * 8 + 4];
            float a[8] = {a0.x, a0.y, a0.z, a0.w, a1.x, a1.y, a1.z, a1.w};
            float b[8] = {b0.x, b0.y, b0.z, b0.w, b1.x, b1.y, b1.z, b1.w};
            #pragma unroll
            for (int i = 0; i < 8; i++)
                #pragma unroll
                for (int j = 0; j < 8; j++)
                    acc[i][j] = fmaf(a[i], b[j], acc[i][j]);
        }
        if (kn < DDIM) {
            const int nb = buf ^ 1;
            As[nb][la_k + 0][la_m] = av.x;
            As[nb][la_k + 1][la_m] = av.y;
            As[nb][la_k + 2][la_m] = av.z;
            As[nb][la_k + 3][la_m] = av.w;
            *(float4*)&Bs[nb][lb_k][lb_n] = bv;
            __syncthreads();
            buf = nb;
        }
    }

    #pragma unroll
    for (int i = 0; i < 8; i++) {
        int r = m0 + ty * 8 + i;
        if (r < cnt) {
            float* crow = g_H + (size_t)(off + r) * FDIM + n0 + tx * 8;
            float4 o0, o1;
            o0.x = gelu_exact(acc[i][0]); o0.y = gelu_exact(acc[i][1]);
            o0.z = gelu_exact(acc[i][2]); o0.w = gelu_exact(acc[i][3]);
            o1.x = gelu_exact(acc[i][4]); o1.y = gelu_exact(acc[i][5]);
            o1.z = gelu_exact(acc[i][6]); o1.w = gelu_exact(acc[i][7]);
            *(float4*)crow       = o0;
            *(float4*)(crow + 4) = o1;
        }
    }
}

// ---------------- K5: Y = w_row * (H @ W2[e]) ----------------
// grid = (DDIM/BN, NTOK/BM, NEXP), block = 256
__global__ __launch_bounds__(256) void gemm2_kernel(const float* __restrict__ W2all) {
    const int e   = blockIdx.z;
    const int cnt = g_count[e];
    const int m0  = blockIdx.y * BM;
    if (m0 >= cnt) return;
    const int n0  = blockIdx.x * BN;
    const int off = g_offset[e];
    const float* Bmat = W2all + (size_t)e * FDIM * DDIM;

    __shared__ float As[2][BK][BM];
    __shared__ float Bs[2][BK][BN];
    __shared__ float wrow[BM];

    const int tid = threadIdx.x;
    if (tid < BM) {
        int r = m0 + tid;
        wrow[tid] = (r < cnt) ? g_w_of_row[off + r] : 0.f;
    }
    __syncthreads();

    const int la_m = tid >> 1;
    const int la_k = (tid & 1) * 4;
    const int lb_k = tid >> 5;
    const int lb_n = (tid & 31) * 4;
    const int tx   = tid & 15;
    const int ty   = tid >> 4;

    const bool avalid = (m0 + la_m) < cnt;
    const float* aptr = g_H + (size_t)(off + (avalid ? (m0 + la_m) : 0)) * FDIM;

    float acc[8][8];
    #pragma unroll
    for (int i = 0; i < 8; i++)
        #pragma unroll
        for (int j = 0; j < 8; j++) acc[i][j] = 0.f;

    float4 av = avalid ? *(const float4*)(aptr + la_k) : make_float4(0, 0, 0, 0);
    float4 bv = *(const float4*)(Bmat + (size_t)lb_k * DDIM + n0 + lb_n);
    As[0][la_k + 0][la_m] = av.x;
    As[0][la_k + 1][la_m] = av.y;
    As[0][la_k + 2][la_m] = av.z;
    As[0][la_k + 3][la_m] = av.w;
    *(float4*)&Bs[0][lb_k][lb_n] = bv;
    __syncthreads();

    int buf = 0;
    #pragma unroll 1
    for (int k0 = 0; k0 < FDIM; k0 += BK) {
        const int kn = k0 + BK;
        if (kn < FDIM) {
            av = avalid ? *(const float4*)(aptr + kn + la_k) : make_float4(0, 0, 0, 0);
            bv = *(const float4*)(Bmat + (size_t)(kn + lb_k) * DDIM + n0 + lb_n);
        }
        #pragma unroll
        for (int k = 0; k < BK; k++) {
            float4 a0 = *(const float4*)&As[buf][k][ty * 8];
            float4 a1 = *(const float4*)&As[buf][k][ty * 8 + 4];
            float4 b0 = *(const float4*)&Bs[buf][k][tx * 8];
            float4 b1 = *(const float4*)&Bs[buf][k][tx * 8 + 4];
            float a[8] = {a0.x, a0.y, a0.z, a0.w, a1.x, a1.y, a1.z, a1.w};
            float b[8] = {b0.x, b0.y, b0.z, b0.w, b1.x, b1.y, b1.z, b1.w};
            #pragma unroll
            for (int i = 0; i < 8; i++)
                #pragma unroll
                for (int j = 0; j < 8; j++)
                    acc[i][j] = fmaf(a[i], b[j], acc[i][j]);
        }
        if (kn < FDIM) {
            const int nb = buf ^ 1;
            As[nb][la_k + 0][la_m] = av.x;
            As[nb][la_k + 1][la_m] = av.y;
            As[nb][la_k + 2][la_m] = av.z;
            As[nb][la_k + 3][la_m] = av.w;
            *(float4*)&Bs[nb][lb_k][lb_n] = bv;
            __syncthreads();
            buf = nb;
        }
    }

    #pragma unroll
    for (int i = 0; i < 8; i++) {
        int r = m0 + ty * 8 + i;
        if (r < cnt) {
            float w = wrow[ty * 8 + i];
            float* crow = g_Y + (size_t)(off + r) * DDIM + n0 + tx * 8;
            float4 o0, o1;
            o0.x = w * acc[i][0]; o0.y = w * acc[i][1];
            o0.z = w * acc[i][2]; o0.w = w * acc[i][3];
            o1.x = w * acc[i][4]; o1.y = w * acc[i][5];
            o1.z = w * acc[i][6]; o1.w = w * acc[i][7];
            *(float4*)crow       = o0;
            *(float4*)(crow + 4) = o1;
        }
    }
}

// ---------------- K6: combine the two expert rows per token ----------------
__global__ void combine_kernel(float* __restrict__ out) {
    int idx = blockIdx.x * blockDim.x + threadIdx.x;   // over NTOK * DDIM / 4
    if (idx >= NTOK * (DDIM / 4)) return;
    int n  = idx >> 8;          // DDIM/4 = 256 float4 per token
    int d4 = idx & 255;
    int r0 = g_row_of_token[2 * n + 0];
    int r1 = g_row_of_token[2 * n + 1];
    float4 a = *(const float4*)(g_Y + (size_t)r0 * DDIM + d4 * 4);
    float4 b = *(const float4*)(g_Y + (size_t)r1 * DDIM + d4 * 4);
    float4 o;
    o.x = a.x + b.x; o.y = a.y + b.y; o.z = a.z + b.z; o.w = a.w + b.w;
    ((float4*)out)[idx] = o;
}

// ---------------- launch ----------------
extern "C" void kernel_launch(void* const* d_in, const int* in_sizes, int n_in,
                              void* d_out, int out_size) {
    const float* x  = (const float*)d_in[0];   // [N, D]
    const float* Wr = (const float*)d_in[1];   // [D, E]
    const float* W1 = (const float*)d_in[2];   // [E, D, F]
    const float* W2 = (const float*)d_in[3];   // [E, F, D]
    float* out = (float*)d_out;                // [N, D]

    zero_kernel<<<1, 32>>>();
    router_kernel<<<64, 256>>>(x, Wr);
    prefix_kernel<<<1, 1>>>();
    dispatch_kernel<<<(NTOK + 255) / 256, 256>>>();
    gemm1_kernel<<<dim3(FDIM / BN, NTOK / BM, NEXP), 256>>>(x, W1);
    gemm2_kernel<<<dim3(DDIM / BN, NTOK / BM, NEXP), 256>>>(W2);
    combine_kernel<<<(NTOK * (DDIM / 4) + 255) / 256, 256>>>(out);
}

// round 5
// speedup vs baseline: 2.6268x; 2.6268x over previous
#include <cuda_runtime.h>
#include <cuda_bf16.h>
#include <math.h>
#include <stdint.h>

#define NTOK 4096   // B*T
#define DDIM 1024
#define FDIM 4096
#define NEXP 8
#define NROWS (NTOK * 2)   // dispatch rows (top-2)

// GEMM tiling: 128x128 CTA tile, K-chunk 16, 2-stage reg->smem double buffer
#define KCH 16
#define APITCH 48                    // 16 bf16 = 32B data padded to 48B (odd 16B units)
#define BPITCH 272                   // 128 bf16 = 256B padded to 272B
#define A_TILE (128 * APITCH)        // 6144 per half (hi or lo)
#define B_TILE (KCH * BPITCH)        // 4352 per half
#define STAGE  (2 * A_TILE + 2 * B_TILE)  // 20992

// ---------------- device scratch (R1-sized footprint) ----------------
__device__ int   g_count[NEXP];
__device__ int   g_cursor[NEXP];
__device__ int   g_offset[NEXP];
__device__ int   g_topk_idx[NTOK * 2];
__device__ float g_topk_w[NTOK * 2];
__device__ int   g_token_of_row[NROWS];
__device__ float g_w_of_row[NROWS];
__device__ int   g_row_of_token[NROWS];
__device__ __align__(16) float g_H[(size_t)NROWS * FDIM];   // 134 MB fp32
__device__ __align__(16) float g_Y[(size_t)NROWS * DDIM];   // 33.5 MB fp32

// ---------------- helpers ----------------
__device__ __forceinline__ uint32_t smem_u32(const void* p) {
    uint32_t a;
    asm("{ .reg .u64 t; cvta.to.shared.u64 t, %1; cvt.u32.u64 %0, t; }" : "=r"(a) : "l"(p));
    return a;
}
__device__ __forceinline__ void ldm_x4(uint32_t (&r)[4], uint32_t a) {
    asm volatile("ldmatrix.sync.aligned.m8n8.x4.shared.b16 {%0,%1,%2,%3}, [%4];"
                 : "=r"(r[0]), "=r"(r[1]), "=r"(r[2]), "=r"(r[3]) : "r"(a));
}
__device__ __forceinline__ void ldm_x4t(uint32_t (&r)[4], uint32_t a) {
    asm volatile("ldmatrix.sync.aligned.m8n8.x4.trans.shared.b16 {%0,%1,%2,%3}, [%4];"
                 : "=r"(r[0]), "=r"(r[1]), "=r"(r[2]), "=r"(r[3]) : "r"(a));
}
__device__ __forceinline__ void mma16816(float (&d)[4], const uint32_t (&a)[4],
                                         uint32_t b0, uint32_t b1) {
    asm volatile("mma.sync.aligned.m16n8k16.row.col.f32.bf16.bf16.f32 "
                 "{%0,%1,%2,%3}, {%4,%5,%6,%7}, {%8,%9}, {%0,%1,%2,%3};"
                 : "+f"(d[0]), "+f"(d[1]), "+f"(d[2]), "+f"(d[3])
                 : "r"(a[0]), "r"(a[1]), "r"(a[2]), "r"(a[3]), "r"(b0), "r"(b1));
}
__device__ __forceinline__ uint32_t pk2(__nv_bfloat16 a, __nv_bfloat16 b) {
    return (uint32_t)__bfloat16_as_ushort(a) | ((uint32_t)__bfloat16_as_ushort(b) << 16);
}
__device__ __forceinline__ float gelu_exact(float v) {
    return 0.5f * v * (1.0f + erff(v * 0.70710678118654752440f));
}
// split 8 fp32 -> 16B bf16-hi + 16B bf16-lo
__device__ __forceinline__ void split8(float4 v0, float4 v1, uint4& hi, uint4& lo) {
    __nv_bfloat16 h0 = __float2bfloat16(v0.x), h1 = __float2bfloat16(v0.y);
    __nv_bfloat16 h2 = __float2bfloat16(v0.z), h3 = __float2bfloat16(v0.w);
    __nv_bfloat16 h4 = __float2bfloat16(v1.x), h5 = __float2bfloat16(v1.y);
    __nv_bfloat16 h6 = __float2bfloat16(v1.z), h7 = __float2bfloat16(v1.w);
    hi.x = pk2(h0, h1); hi.y = pk2(h2, h3); hi.z = pk2(h4, h5); hi.w = pk2(h6, h7);
    lo.x = pk2(__float2bfloat16(v0.x - __bfloat162float(h0)),
               __float2bfloat16(v0.y - __bfloat162float(h1)));
    lo.y = pk2(__float2bfloat16(v0.z - __bfloat162float(h2)),
               __float2bfloat16(v0.w - __bfloat162float(h3)));
    lo.z = pk2(__float2bfloat16(v1.x - __bfloat162float(h4)),
               __float2bfloat16(v1.y - __bfloat162float(h5)));
    lo.w = pk2(__float2bfloat16(v1.z - __bfloat162float(h6)),
               __float2bfloat16(v1.w - __bfloat162float(h7)));
}

// ---------------- K0-K3: routing (unchanged from passing R1) ----------------
__global__ void zero_kernel() {
    int t = threadIdx.x;
    if (t < NEXP) { g_count[t] = 0; g_cursor[t] = 0; }
}

__global__ void router_kernel(const float* __restrict__ x,
                              const float* __restrict__ Wr) {
    int gwarp  = (blockIdx.x * blockDim.x + threadIdx.x) >> 5;
    int lane   = threadIdx.x & 31;
    int nwarps = (gridDim.x * blockDim.x) >> 5;
    for (int n = gwarp; n < NTOK; n += nwarps) {
        const float* xr = x + (size_t)n * DDIM;
        float acc[NEXP];
        #pragma unroll
        for (int e = 0; e < NEXP; e++) acc[e] = 0.f;
        for (int d = lane; d < DDIM; d += 32) {
            float xv = xr[d];
            const float* wr = Wr + (size_t)d * NEXP;
            float4 w0 = *(const float4*)(wr);
            float4 w1 = *(const float4*)(wr + 4);
            acc[0] = fmaf(xv, w0.x, acc[0]); acc[1] = fmaf(xv, w0.y, acc[1]);
            acc[2] = fmaf(xv, w0.z, acc[2]); acc[3] = fmaf(xv, w0.w, acc[3]);
            acc[4] = fmaf(xv, w1.x, acc[4]); acc[5] = fmaf(xv, w1.y, acc[5]);
            acc[6] = fmaf(xv, w1.z, acc[6]); acc[7] = fmaf(xv, w1.w, acc[7]);
        }
        #pragma unroll
        for (int e = 0; e < NEXP; e++)
            #pragma unroll
            for (int o = 16; o > 0; o >>= 1)
                acc[e] += __shfl_xor_sync(0xFFFFFFFFu, acc[e], o);
        if (lane == 0) {
            int i0 = 0; float v0 = acc[0];
            #pragma unroll
            for (int e = 1; e < NEXP; e++)
                if (acc[e] > v0) { v0 = acc[e]; i0 = e; }
            int i1 = -1; float v1 = -3.4e38f;
            #pragma unroll
            for (int e = 0; e < NEXP; e++)
                if (e != i0 && acc[e] > v1) { v1 = acc[e]; i1 = e; }
            float e1 = __expf(v1 - v0);
            float inv = 1.0f / (1.0f + e1);
            g_topk_idx[2 * n + 0] = i0;
            g_topk_idx[2 * n + 1] = i1;
            g_topk_w[2 * n + 0] = inv;
            g_topk_w[2 * n + 1] = e1 * inv;
            atomicAdd(&g_count[i0], 1);
            atomicAdd(&g_count[i1], 1);
        }
    }
}

__global__ void prefix_kernel() {
    int s = 0;
    for (int e = 0; e < NEXP; e++) { g_offset[e] = s; s += g_count[e]; }
}

__global__ void dispatch_kernel() {
    int n = blockIdx.x * blockDim.x + threadIdx.x;
    if (n >= NTOK) return;
    #pragma unroll
    for (int s = 0; s < 2; s++) {
        int e   = g_topk_idx[2 * n + s];
        int pos = atomicAdd(&g_cursor[e], 1);
        int row = g_offset[e] + pos;
        g_token_of_row[row] = n;
        g_w_of_row[row]     = g_topk_w[2 * n + s];
        g_row_of_token[2 * n + s] = row;
    }
}

// ---------------- K4/K5: split-bf16 mma GEMM, sync staging ----------------
// PH1: H = gelu(gather(X) @ W1[e]) fp32 ; PH2: Y = w * (H @ W2[e]) fp32
template<bool PH1>
__global__ __launch_bounds__(256) void moe_gemm_kernel(const float* __restrict__ Aglob,
                                                       const float* __restrict__ Wglob) {
    constexpr int K  = PH1 ? DDIM : FDIM;
    constexpr int NT = PH1 ? FDIM : DDIM;
    constexpr int NC = K / KCH;

    const int e   = blockIdx.z;
    const int cnt = g_count[e];
    const int m0  = blockIdx.x * 128;
    if (m0 >= cnt) return;
    const int n0  = blockIdx.y * 128;
    const int off = g_offset[e];
    const size_t rowbase = (size_t)off + m0;
    const float* Bsrc = Wglob + (size_t)e * K * NT + n0;

    __shared__ __align__(128) char smbuf[2][STAGE];
    __shared__ int   toks[128];
    __shared__ float wrow[128];

    const int tid  = threadIdx.x;
    const int warp = tid >> 5, lane = tid & 31;
    const int wm = warp & 1, wn = warp >> 1;    // 2x4 warps: 64m x 32n each

    if (tid < 128) {
        int r = m0 + tid;
        if (PH1) toks[tid] = (r < cnt) ? g_token_of_row[off + r] : g_token_of_row[off];
        else     wrow[tid] = (r < cnt) ? g_w_of_row[off + r] : 0.f;
    }
    __syncthreads();

    // loader roles
    const int a_row = tid >> 1, a_seg = tid & 1;   // 128 rows x 2 8-elem segs
    const int b_k   = tid >> 4, b_seg = tid & 15;  // 16 k-rows x 16 8-elem segs
    const float* aptr;
    if (PH1) {
        aptr = Aglob + (size_t)toks[a_row] * DDIM;
    } else {
        size_t ra = rowbase + a_row;
        if (ra >= NROWS) ra = 0;
        aptr = Aglob + ra * (size_t)FDIM;
    }

    float4 pa0, pa1, pb0, pb1;
    // prefetch chunk 0
    pa0 = *(const float4*)(aptr + a_seg * 8);
    pa1 = *(const float4*)(aptr + a_seg * 8 + 4);
    pb0 = *(const float4*)(Bsrc + (size_t)b_k * NT + b_seg * 8);
    pb1 = *(const float4*)(Bsrc + (size_t)b_k * NT + b_seg * 8 + 4);
    {   // store stage 0
        uint4 hi, lo;
        split8(pa0, pa1, hi, lo);
        *(uint4*)(smbuf[0] + a_row * APITCH + a_seg * 16) = hi;
        *(uint4*)(smbuf[0] + A_TILE + a_row * APITCH + a_seg * 16) = lo;
        split8(pb0, pb1, hi, lo);
        *(uint4*)(smbuf[0] + 2 * A_TILE + b_k * BPITCH + b_seg * 16) = hi;
        *(uint4*)(smbuf[0] + 2 * A_TILE + B_TILE + b_k * BPITCH + b_seg * 16) = lo;
    }
    __syncthreads();

    float acc[4][4][4];
    #pragma unroll
    for (int i = 0; i < 4; i++)
        #pragma unroll
        for (int j = 0; j < 4; j++)
            #pragma unroll
            for (int q = 0; q < 4; q++) acc[i][j][q] = 0.f;

    const uint32_t smb = smem_u32(smbuf);
    const int lrow = lane & 15;       // ldmatrix row-within-16
    const int lk   = lane >> 4;       // 0/1 -> +16B (8 elems)
    const uint32_t aoff = (uint32_t)((wm * 64 + lrow) * APITCH + lk * 16);
    const uint32_t boff = (uint32_t)(2 * A_TILE + lrow * BPITCH + wn * 64 + lk * 16);

    #pragma unroll 1
    for (int c = 0; c < NC; c++) {
        if (c + 1 < NC) {   // prefetch next chunk into regs (overlaps mma below)
            int kc = (c + 1) * KCH;
            pa0 = *(const float4*)(aptr + kc + a_seg * 8);
            pa1 = *(const float4*)(aptr + kc + a_seg * 8 + 4);
            pb0 = *(const float4*)(Bsrc + (size_t)(kc + b_k) * NT + b_seg * 8);
            pb1 = *(const float4*)(Bsrc + (size_t)(kc + b_k) * NT + b_seg * 8 + 4);
        }

        // compute on stage c&1
        uint32_t stb = smb + (uint32_t)((c & 1) * STAGE);
        uint32_t bh[2][4], bl[2][4];
        #pragma unroll
        for (int p = 0; p < 2; p++) {
            uint32_t b = stb + boff + p * 32;
            ldm_x4t(bh[p], b);
            ldm_x4t(bl[p], b + B_TILE);
        }
        #pragma unroll
        for (int mi = 0; mi < 4; mi++) {
            uint32_t ah[4], al[4];
            uint32_t a = stb + aoff + mi * (16 * APITCH);
            ldm_x4(ah, a);
            ldm_x4(al, a + A_TILE);
            #pragma unroll
            for (int ni = 0; ni < 4; ni++) {
                int p = ni >> 1, q = (ni & 1) * 2;
                mma16816(acc[mi][ni], ah, bh[p][q], bh[p][q + 1]);
                mma16816(acc[mi][ni], ah, bl[p][q], bl[p][q + 1]);
                mma16816(acc[mi][ni], al, bh[p][q], bh[p][q + 1]);
            }
        }
        __syncthreads();            // all warps done reading stage c&1
        if (c + 1 < NC) {           // store prefetched chunk into other stage
            char* dst = smbuf[(c + 1) & 1];
            uint4 hi, lo;
            split8(pa0, pa1, hi, lo);
            *(uint4*)(dst + a_row * APITCH + a_seg * 16) = hi;
            *(uint4*)(dst + A_TILE + a_row * APITCH + a_seg * 16) = lo;
            split8(pb0, pb1, hi, lo);
            *(uint4*)(dst + 2 * A_TILE + b_k * BPITCH + b_seg * 16) = hi;
            *(uint4*)(dst + 2 * A_TILE + B_TILE + b_k * BPITCH + b_seg * 16) = lo;
        }
        __syncthreads();
    }

    // ---------------- epilogue ----------------
    const int ro  = lane >> 2;
    const int cp2 = (lane & 3) * 2;
    #pragma unroll
    for (int mi = 0; mi < 4; mi++)
        #pragma unroll
        for (int half = 0; half < 2; half++) {
            int lr = wm * 64 + mi * 16 + half * 8 + ro;
            if (m0 + lr < cnt) {
                size_t gr = rowbase + lr;
                if (PH1) {
                    float* od = g_H + gr * (size_t)FDIM + n0 + wn * 32 + cp2;
                    #pragma unroll
                    for (int ni = 0; ni < 4; ni++) {
                        float2 v;
                        v.x = gelu_exact(acc[mi][ni][half * 2 + 0]);
                        v.y = gelu_exact(acc[mi][ni][half * 2 + 1]);
                        *(float2*)(od + ni * 8) = v;
                    }
                } else {
                    float w = wrow[lr];
                    float* od = g_Y + gr * (size_t)DDIM + n0 + wn * 32 + cp2;
                    #pragma unroll
                    for (int ni = 0; ni < 4; ni++) {
                        float2 v;
                        v.x = w * acc[mi][ni][half * 2 + 0];
                        v.y = w * acc[mi][ni][half * 2 + 1];
                        *(float2*)(od + ni * 8) = v;
                    }
                }
            }
        }
}

// ---------------- K6: combine ----------------
__global__ void combine_kernel(float* __restrict__ out) {
    int idx = blockIdx.x * blockDim.x + threadIdx.x;
    if (idx >= NTOK * (DDIM / 4)) return;
    int n  = idx >> 8;
    int d4 = idx & 255;
    int r0 = g_row_of_token[2 * n + 0];
    int r1 = g_row_of_token[2 * n + 1];
    float4 a = *(const float4*)(g_Y + (size_t)r0 * DDIM + d4 * 4);
    float4 b = *(const float4*)(g_Y + (size_t)r1 * DDIM + d4 * 4);
    float4 o;
    o.x = a.x + b.x; o.y = a.y + b.y; o.z = a.z + b.z; o.w = a.w + b.w;
    ((float4*)out)[idx] = o;
}

// ---------------- launch ----------------
extern "C" void kernel_launch(void* const* d_in, const int* in_sizes, int n_in,
                              void* d_out, int out_size) {
    const float* x  = (const float*)d_in[0];
    const float* Wr = (const float*)d_in[1];
    const float* W1 = (const float*)d_in[2];   // [E][D][F]
    const float* W2 = (const float*)d_in[3];   // [E][F][D]
    float* out = (float*)d_out;

    zero_kernel<<<1, 32>>>();
    router_kernel<<<64, 256>>>(x, Wr);
    prefix_kernel<<<1, 1>>>();
    dispatch_kernel<<<(NTOK + 255) / 256, 256>>>();

    float* hptr = nullptr;
    cudaGetSymbolAddress((void**)&hptr, g_H);
    moe_gemm_kernel<true><<<dim3(NROWS / 128, FDIM / 128, NEXP), 256>>>(x, W1);
    moe_gemm_kernel<false><<<dim3(NROWS / 128, DDIM / 128, NEXP), 256>>>(hptr, W2);
    combine_kernel<<<(NTOK * (DDIM / 4) + 255) / 256, 256>>>(out);
}